// round 5
// baseline (speedup 1.0000x reference)
#include <cuda_runtime.h>
#include <cstdint>
#include <math.h>

// ---------------------------------------------------------------------------
// Problem constants
// ---------------------------------------------------------------------------
constexpr int Bc = 8;
constexpr int C  = 1024;
constexpr int Ci = 512;
constexpr int Nd = 48 * 48;          // 2304
constexpr int Na = 16 * 16;          // 256
constexpr int R  = 64;               // C / 16
constexpr float BN_INV = 0.9999950000374997f;  // 1/sqrt(1+1e-5)

// ---------------------------------------------------------------------------
// Device scratch (static)
// ---------------------------------------------------------------------------
__device__ float g_detT  [Bc * Nd * C];    // detect^T  [Nd, C]
__device__ float g_aimT  [Bc * Na * C];    // aim^T     [Na, C]
__device__ float g_dx    [Bc * Ci * Nd];   // d_x   [Ci, Nd]
__device__ float g_phx   [Bc * Nd * Ci];   // phi_x [Nd, Ci]
__device__ float g_ax    [Bc * Ci * Na];   // a_x   [Ci, Na]
__device__ float g_thx   [Bc * Na * Ci];   // theta [Na, Ci]
__device__ float g_fm    [Bc * Na * Nd];   // f     [Na, Nd]
__device__ float g_fT    [Bc * Nd * Na];   // f^T   [Nd, Na]
__device__ float g_nap   [Bc * Na * Ci];   // nap   [Na, Ci]
__device__ float g_ndp   [Bc * Nd * Ci];   // ndp   [Nd, Ci]
__device__ float g_nonaim[Bc * C  * Na];   // non_aim [C, Na]
__device__ float g_pooled[Bc * 2  * C];

// ---------------------------------------------------------------------------
// mma / cp.async helpers
// ---------------------------------------------------------------------------
__device__ __forceinline__ void mma8(float* d, const uint32_t* a, const uint32_t* b) {
    asm volatile(
        "mma.sync.aligned.m16n8k8.row.col.f32.tf32.tf32.f32 "
        "{%0,%1,%2,%3}, {%4,%5,%6,%7}, {%8,%9}, {%0,%1,%2,%3};"
        : "+f"(d[0]), "+f"(d[1]), "+f"(d[2]), "+f"(d[3])
        : "r"(a[0]), "r"(a[1]), "r"(a[2]), "r"(a[3]), "r"(b[0]), "r"(b[1]));
}
__device__ __forceinline__ uint32_t smem_u32(const void* p) {
    uint32_t a;
    asm("{ .reg .u64 t; cvta.to.shared.u64 t, %1; cvt.u32.u64 %0, t; }" : "=r"(a) : "l"(p));
    return a;
}
__device__ __forceinline__ void cpa16(uint32_t s, const void* g) {
    asm volatile("cp.async.cg.shared.global [%0], [%1], 16;" :: "r"(s), "l"(g));
}
#define CPA_COMMIT() asm volatile("cp.async.commit_group;" ::: "memory")
#define CPA_WAIT1()  asm volatile("cp.async.wait_group 1;" ::: "memory")
#define CPA_WAIT0()  asm volatile("cp.async.wait_group 0;" ::: "memory")

// ---------------------------------------------------------------------------
// tf32 mma.sync GEMM:  D[M,N] = alpha * A[M,K] * B[N,K]^T  (+ epilogue)
//   Block 128x128, BK=32 double-buffered via cp.async, 4 warps (2m x 2n),
//   warp tile 64x64.  Operands fed as raw fp32 bits (tf32 truncation).
//   Smem k-stride 36 words -> fragment LDS bank = 4g+t, conflict-free.
//   Requires M%128==0, N%128==0, K%32==0, row stride == K.
//   EPI 0: alpha*acc (+ bM[m] if BMODE==1, + bN[n] if BMODE==2)
//   EPI 1: bng[m]*BN_INV*(acc+bM[m]) + bnb[m] + resid[m*ldc+n]
//   EPI 2: EPI1 value v; additionally out2 = v * cw[bz*M + m]
// ---------------------------------------------------------------------------
constexpr int SA    = 36;                  // padded k-stride in words (32 + 4)
constexpr int HTILE = 128 * SA;            // words per operand per stage
constexpr int STAGE = 2 * HTILE;           // words per stage (A then B)
constexpr int GSMEM = 2 * STAGE * 4;       // bytes: 73728

template<int EPI, int BMODE>
__global__ void __launch_bounds__(128)
tgemm(const float* __restrict__ A, const float* __restrict__ B,
      float* __restrict__ Co,
      int K, int ldc, long strA, long strB, long strC, float alpha,
      const float* __restrict__ bM, const float* __restrict__ bN,
      const float* __restrict__ bng, const float* __restrict__ bnb,
      const float* __restrict__ resid, long sR,
      const float* __restrict__ cw, float* __restrict__ out2)
{
    extern __shared__ uint32_t sm[];
    const uint32_t smb = smem_u32(sm);

    const int tid = threadIdx.x, lane = tid & 31, wid = tid >> 5;
    const int wm = wid & 1, wn = wid >> 1;           // warp grid 2(m) x 2(n)
    const int bz = blockIdx.z;
    const int bm = blockIdx.y * 128, bn = blockIdx.x * 128;

    // loader: thread t owns row t of A tile and row t of B tile (128B each)
    const float* apg = A + (long)bz * strA + (long)(bm + tid) * K;
    const float* bpg = B + (long)bz * strB + (long)(bn + tid) * K;
    const uint32_t sa_byte = smb + (uint32_t)(tid * SA) * 4;           // + st*STAGE*4
    const uint32_t sb_byte = smb + (uint32_t)(HTILE + tid * SA) * 4;

    auto loadt = [&](int kt, int st) {
        const float* ag = apg + kt * 32;
        const float* bg = bpg + kt * 32;
        const uint32_t ab = sa_byte + st * (STAGE * 4);
        const uint32_t bb = sb_byte + st * (STAGE * 4);
        #pragma unroll
        for (int j = 0; j < 8; j++) cpa16(ab + j * 16, ag + j * 4);
        #pragma unroll
        for (int j = 0; j < 8; j++) cpa16(bb + j * 16, bg + j * 4);
    };

    float acc[4][8][4];
    #pragma unroll
    for (int i = 0; i < 4; i++)
        #pragma unroll
        for (int j = 0; j < 8; j++)
            #pragma unroll
            for (int q = 0; q < 4; q++) acc[i][j][q] = 0.f;

    const int g = lane >> 2, t = lane & 3;
    auto compute = [&](int st) {
        const uint32_t* sAp = sm + st * STAGE;
        const uint32_t* sBp = sAp + HTILE;
        #pragma unroll
        for (int k8 = 0; k8 < 4; k8++) {
            const int kb = k8 * 8;
            uint32_t af[4][4];
            #pragma unroll
            for (int mi = 0; mi < 4; mi++) {
                const uint32_t* p = sAp + (wm * 64 + mi * 16 + g) * SA + kb + t;
                af[mi][0] = p[0];
                af[mi][1] = p[8 * SA];
                af[mi][2] = p[4];
                af[mi][3] = p[8 * SA + 4];
            }
            #pragma unroll
            for (int ni = 0; ni < 8; ni++) {
                const uint32_t* p = sBp + (wn * 64 + ni * 8 + g) * SA + kb + t;
                uint32_t bf[2] = { p[0], p[4] };
                #pragma unroll
                for (int mi = 0; mi < 4; mi++) mma8(acc[mi][ni], af[mi], bf);
            }
        }
    };

    const int nk = K / 32;          // all K here >= 256 -> nk >= 8
    loadt(0, 0); CPA_COMMIT();
    loadt(1, 1); CPA_COMMIT();
    for (int kt = 0; kt < nk; kt++) {
        const int s = kt & 1;
        if (kt + 1 < nk) { CPA_WAIT1(); } else { CPA_WAIT0(); }
        __syncthreads();
        compute(s);
        if (kt + 2 < nk) {
            __syncthreads();          // all warps done reading stage s
            loadt(kt + 2, s); CPA_COMMIT();
        }
    }

    // ---- epilogue ----
    const int t2 = (lane & 3) * 2;
    #pragma unroll
    for (int mi = 0; mi < 4; mi++) {
        #pragma unroll
        for (int half = 0; half < 2; half++) {
            const int m = bm + wm * 64 + mi * 16 + half * 8 + g;
            float addM = 0.f, sc = 1.f, be = 0.f, gwv = 0.f;
            if constexpr (EPI == 0) {
                if constexpr (BMODE == 1) addM = bM[m];
            } else {
                addM = bM[m]; sc = bng[m] * BN_INV; be = bnb[m];
            }
            float* crow = Co + (long)bz * strC + (long)m * ldc;
            const float* rrow = nullptr;
            float* o2row = nullptr;
            if constexpr (EPI >= 1) rrow = resid + (long)bz * sR + (long)m * ldc;
            if constexpr (EPI == 2) {
                o2row = out2 + (long)bz * strC + (long)m * ldc;
                gwv = cw[(long)bz * (gridDim.y * 128) + m];
            }
            #pragma unroll
            for (int ni = 0; ni < 8; ni++) {
                const int n = bn + wn * 64 + ni * 8 + t2;
                const float c0 = acc[mi][ni][half * 2 + 0];
                const float c1 = acc[mi][ni][half * 2 + 1];
                float2 o;
                if constexpr (EPI == 0) {
                    o.x = alpha * c0 + addM;
                    o.y = alpha * c1 + addM;
                    if constexpr (BMODE == 2) { o.x += bN[n]; o.y += bN[n + 1]; }
                } else {
                    float2 rv = *(const float2*)&rrow[n];
                    o.x = sc * (c0 + addM) + be + rv.x;
                    o.y = sc * (c1 + addM) + be + rv.y;
                }
                *(float2*)&crow[n] = o;
                if constexpr (EPI == 2) {
                    float2 o2 = { o.x * gwv, o.y * gwv };
                    *(float2*)&o2row[n] = o2;
                }
            }
        }
    }
}

// ---------------------------------------------------------------------------
// Transpose: src [rows][cols] -> dst [cols][rows], per batch z
// ---------------------------------------------------------------------------
__global__ void transpose_k(const float* __restrict__ src, float* __restrict__ dst,
                            int rows, int cols)
{
    __shared__ float t[32][33];
    const long bo = (long)blockIdx.z * rows * cols;
    const int c0 = blockIdx.x * 32, r0 = blockIdx.y * 32;
    const int tx = threadIdx.x, ty = threadIdx.y;
    #pragma unroll
    for (int i = 0; i < 32; i += 8)
        t[ty + i][tx] = src[bo + (long)(r0 + ty + i) * cols + c0 + tx];
    __syncthreads();
    #pragma unroll
    for (int i = 0; i < 32; i += 8)
        dst[bo + (long)(c0 + ty + i) * rows + r0 + tx] = t[tx][ty + i];
}

// ---------------------------------------------------------------------------
// Avg+Max pooling over non_aim spatial dim: one warp per (b,c)
// ---------------------------------------------------------------------------
__global__ void pool_k(const float* __restrict__ na, float* __restrict__ pooled)
{
    const int gw = (int)((blockIdx.x * (long)blockDim.x + threadIdx.x) >> 5);
    const int lane = threadIdx.x & 31;
    if (gw >= Bc * C) return;
    const float* p = na + (long)gw * Na;
    float s = 0.f, m = -3.4e38f;
    for (int i = lane; i < Na; i += 32) { float v = p[i]; s += v; m = fmaxf(m, v); }
    #pragma unroll
    for (int o = 16; o; o >>= 1) {
        s += __shfl_xor_sync(0xffffffffu, s, o);
        m = fmaxf(m, __shfl_xor_sync(0xffffffffu, m, o));
    }
    if (lane == 0) {
        const int b = gw / C, c = gw % C;
        pooled[(long)b * 2 * C + c]     = s * (1.f / Na);
        pooled[(long)b * 2 * C + C + c] = m;
    }
}

// ---------------------------------------------------------------------------
// Channel gate MLP + sigmoid, one block per batch
// ---------------------------------------------------------------------------
__global__ void gate_k(const float* __restrict__ pooled,
                       const float* __restrict__ w1, const float* __restrict__ b1,
                       const float* __restrict__ w2, const float* __restrict__ b2,
                       float* __restrict__ cw)
{
    __shared__ float sv[2 * C];
    __shared__ float h[2][R];
    __shared__ float hs[R];
    const int b = blockIdx.x, tid = threadIdx.x;
    for (int i = tid; i < 2 * C; i += blockDim.x)
        sv[i] = pooled[(long)b * 2 * C + i];
    __syncthreads();
    if (tid < 2 * R) {
        const int which = tid / R, r = tid % R;
        const float* v = sv + which * C;
        const float* wr = w1 + r * C;
        float acc = b1[r];
        for (int c = 0; c < C; c++) acc += wr[c] * v[c];
        h[which][r] = fmaxf(acc, 0.f);
    }
    __syncthreads();
    if (tid < R) hs[tid] = h[0][tid] + h[1][tid];
    __syncthreads();
    for (int c = tid; c < C; c += blockDim.x) {
        const float* wc = w2 + c * R;
        float acc = 2.f * b2[c];
        #pragma unroll 8
        for (int r = 0; r < R; r++) acc += wc[r] * hs[r];
        cw[(long)b * C + c] = 1.f / (1.f + expf(-acc));
    }
}

// ---------------------------------------------------------------------------
// Channel scaling (act_aim): dst = src * cw[b*C + c]
// ---------------------------------------------------------------------------
__global__ void scale_k(const float* __restrict__ src, const float* __restrict__ cw,
                        float* __restrict__ dst, int q_div, long total4)
{
    const long i = blockIdx.x * (long)blockDim.x + threadIdx.x;
    if (i >= total4) return;
    const float w = cw[i / q_div];
    float4 v = ((const float4*)src)[i];
    v.x *= w; v.y *= w; v.z *= w; v.w *= w;
    ((float4*)dst)[i] = v;
}

// ---------------------------------------------------------------------------
// Launch
// ---------------------------------------------------------------------------
extern "C" void kernel_launch(void* const* d_in, const int* in_sizes, int n_in,
                              void* d_out, int out_size)
{
    (void)in_sizes; (void)n_in; (void)out_size;
    const float* detect = (const float*)d_in[0];
    const float* aim    = (const float*)d_in[1];
    const float* g_w    = (const float*)d_in[2];
    const float* g_b    = (const float*)d_in[3];
    const float* th_w   = (const float*)d_in[4];
    const float* th_b   = (const float*)d_in[5];
    const float* ph_w   = (const float*)d_in[6];
    const float* ph_b   = (const float*)d_in[7];
    const float* W_w    = (const float*)d_in[8];
    const float* W_b    = (const float*)d_in[9];
    const float* W_bn_g = (const float*)d_in[10];
    const float* W_bn_b = (const float*)d_in[11];
    const float* Q_w    = (const float*)d_in[12];
    const float* Q_b    = (const float*)d_in[13];
    const float* Q_bn_g = (const float*)d_in[14];
    const float* Q_bn_b = (const float*)d_in[15];
    const float* m1_w   = (const float*)d_in[16];
    const float* m1_b   = (const float*)d_in[17];
    const float* m2_w   = (const float*)d_in[18];
    const float* m2_b   = (const float*)d_in[19];
    float* out = (float*)d_out;

    float *detT, *aimT, *dx, *phx, *ax, *thx, *fm, *fT, *nap, *ndp, *nonaim, *pooled;
    cudaGetSymbolAddress((void**)&detT,   g_detT);
    cudaGetSymbolAddress((void**)&aimT,   g_aimT);
    cudaGetSymbolAddress((void**)&dx,     g_dx);
    cudaGetSymbolAddress((void**)&phx,    g_phx);
    cudaGetSymbolAddress((void**)&ax,     g_ax);
    cudaGetSymbolAddress((void**)&thx,    g_thx);
    cudaGetSymbolAddress((void**)&fm,     g_fm);
    cudaGetSymbolAddress((void**)&fT,     g_fT);
    cudaGetSymbolAddress((void**)&nap,    g_nap);
    cudaGetSymbolAddress((void**)&ndp,    g_ndp);
    cudaGetSymbolAddress((void**)&nonaim, g_nonaim);
    cudaGetSymbolAddress((void**)&pooled, g_pooled);

    const long offNonDet = 0;
    const long offActDet = (long)Bc * C * Nd;
    const long offActAim = 2 * offActDet;
    const long offCw     = offActAim + (long)Bc * C * Na;

    cudaFuncSetAttribute(tgemm<0,0>, cudaFuncAttributeMaxDynamicSharedMemorySize, GSMEM);
    cudaFuncSetAttribute(tgemm<0,1>, cudaFuncAttributeMaxDynamicSharedMemorySize, GSMEM);
    cudaFuncSetAttribute(tgemm<0,2>, cudaFuncAttributeMaxDynamicSharedMemorySize, GSMEM);
    cudaFuncSetAttribute(tgemm<1,0>, cudaFuncAttributeMaxDynamicSharedMemorySize, GSMEM);
    cudaFuncSetAttribute(tgemm<2,0>, cudaFuncAttributeMaxDynamicSharedMemorySize, GSMEM);

    // T0: transposes (detect/aim are [C, N]; GEMMs want K=C contiguous rows)
    transpose_k<<<dim3(Nd / 32, C / 32, Bc), dim3(32, 8)>>>(detect, detT, C, Nd);
    transpose_k<<<dim3(Na / 32, C / 32, Bc), dim3(32, 8)>>>(aim,    aimT, C, Na);

    // G1: d_x[Ci,Nd] = g_w * detT^T + g_b[m]
    tgemm<0,1><<<dim3(Nd/128, Ci/128, Bc), 128, GSMEM>>>(
        g_w, detT, dx, C, Nd, 0, (long)Nd*C, (long)Ci*Nd, 1.f,
        g_b, nullptr, nullptr, nullptr, nullptr, 0, nullptr, nullptr);
    // G2: phi_x[Nd,Ci] = detT * ph_w^T + ph_b[n]
    tgemm<0,2><<<dim3(Ci/128, Nd/128, Bc), 128, GSMEM>>>(
        detT, ph_w, phx, C, Ci, (long)Nd*C, 0, (long)Nd*Ci, 1.f,
        nullptr, ph_b, nullptr, nullptr, nullptr, 0, nullptr, nullptr);
    // G3: a_x[Ci,Na] = g_w * aimT^T + g_b[m]
    tgemm<0,1><<<dim3(Na/128, Ci/128, Bc), 128, GSMEM>>>(
        g_w, aimT, ax, C, Na, 0, (long)Na*C, (long)Ci*Na, 1.f,
        g_b, nullptr, nullptr, nullptr, nullptr, 0, nullptr, nullptr);
    // G4: theta_x[Na,Ci] = aimT * th_w^T + th_b[n]
    tgemm<0,2><<<dim3(Ci/128, Na/128, Bc), 128, GSMEM>>>(
        aimT, th_w, thx, C, Ci, (long)Na*C, 0, (long)Na*Ci, 1.f,
        nullptr, th_b, nullptr, nullptr, nullptr, 0, nullptr, nullptr);
    // G5: f[Na,Nd] = theta * phi^T
    tgemm<0,0><<<dim3(Nd/128, Na/128, Bc), 128, GSMEM>>>(
        thx, phx, fm, Ci, Nd, (long)Na*Ci, (long)Nd*Ci, (long)Na*Nd, 1.f,
        nullptr, nullptr, nullptr, nullptr, nullptr, 0, nullptr, nullptr);
    // G5b: fT[Nd,Na] = phi * theta^T
    tgemm<0,0><<<dim3(Na/128, Nd/128, Bc), 128, GSMEM>>>(
        phx, thx, fT, Ci, Na, (long)Nd*Ci, (long)Na*Ci, (long)Nd*Na, 1.f,
        nullptr, nullptr, nullptr, nullptr, nullptr, 0, nullptr, nullptr);
    // G6: nap[Na,Ci] = (1/Nd) f * d_x^T
    tgemm<0,0><<<dim3(Ci/128, Na/128, Bc), 128, GSMEM>>>(
        fm, dx, nap, Nd, Ci, (long)Na*Nd, (long)Ci*Nd, (long)Na*Ci, 1.f/Nd,
        nullptr, nullptr, nullptr, nullptr, nullptr, 0, nullptr, nullptr);
    // G7: ndp[Nd,Ci] = (1/Na) fT * a_x^T
    tgemm<0,0><<<dim3(Ci/128, Nd/128, Bc), 128, GSMEM>>>(
        fT, ax, ndp, Na, Ci, (long)Nd*Na, (long)Ci*Na, (long)Nd*Ci, 1.f/Na,
        nullptr, nullptr, nullptr, nullptr, nullptr, 0, nullptr, nullptr);
    // G8: non_aim[C,Na] = bn(W_w * nap^T + W_b) + aim
    tgemm<1,0><<<dim3(Na/128, C/128, Bc), 128, GSMEM>>>(
        W_w, nap, nonaim, Ci, Na, 0, (long)Na*Ci, (long)C*Na, 1.f,
        W_b, nullptr, W_bn_g, W_bn_b, aim, (long)C*Na, nullptr, nullptr);
    // pool + gate
    pool_k<<<(Bc * C) / 8, 256>>>(nonaim, pooled);
    gate_k<<<Bc, 256>>>(pooled, m1_w, m1_b, m2_w, m2_b, out + offCw);
    // G9: non_det[C,Nd] = bn(Q_w * ndp^T + Q_b) + detect ; act_det fused
    tgemm<2,0><<<dim3(Nd/128, C/128, Bc), 128, GSMEM>>>(
        Q_w, ndp, out + offNonDet, Ci, Nd, 0, (long)Nd*Ci, (long)C*Nd, 1.f,
        Q_b, nullptr, Q_bn_g, Q_bn_b, detect, (long)C*Nd,
        out + offCw, out + offActDet);
    // act_aim = non_aim * cw
    const long t4a = (long)Bc * C * Na / 4;
    scale_k<<<(unsigned)((t4a + 255) / 256), 256>>>(
        nonaim, out + offCw, out + offActAim, Na / 4, t4a);
}